// round 10
// baseline (speedup 1.0000x reference)
#include <cuda_runtime.h>
#include <cuda_fp16.h>

#define TT 8
#define G  16
#define GG 256
#define DD 64
#define THRS 0.5f

// slot-spread accumulators: 0 wl, 1 pool, 2 obj, 3 pres, 4 flowsq, 5 sumzp, 6 sumflow
__device__ double g_slot[7][16];
__device__ unsigned g_ctr;

typedef unsigned long long u64;

__device__ __forceinline__ float wsum(float v) {
#pragma unroll
    for (int s = 16; s > 0; s >>= 1) v += __shfl_xor_sync(0xffffffffu, v, s);
    return v;
}

// ---- packed f32x2 helpers (exact wl path) ----
__device__ __forceinline__ u64 mkf(float lo, float hi) {
    u64 r; asm("mov.b64 %0, {%1, %2};" : "=l"(r) : "f"(lo), "f"(hi)); return r;
}
__device__ __forceinline__ u64 ffma2(u64 a, u64 b, u64 c) {
    u64 r; asm("fma.rn.f32x2 %0, %1, %2, %3;" : "=l"(r) : "l"(a), "l"(b), "l"(c)); return r;
}
__device__ __forceinline__ float lohisum(u64 v) {
    unsigned a, b; asm("mov.b64 {%0, %1}, %2;" : "=r"(a), "=r"(b) : "l"(v));
    return __uint_as_float(a) + __uint_as_float(b);
}

// ---- fp16x2 helpers ----
__device__ __forceinline__ unsigned pkh(float e0, float e1) {
    unsigned r;
    asm("cvt.rn.f16x2.f32 %0, %1, %2;" : "=r"(r) : "f"(e1), "f"(e0));
    return r;  // e0 in lo half, e1 in hi half
}
__device__ __forceinline__ unsigned hfma2(unsigned a, unsigned b, unsigned c) {
    unsigned r; asm("fma.rn.f16x2 %0, %1, %2, %3;" : "=r"(r) : "r"(a), "r"(b), "r"(c)); return r;
}
__device__ __forceinline__ unsigned hmul2(unsigned a, unsigned b) {
    unsigned r; asm("mul.rn.f16x2 %0, %1, %2;" : "=r"(r) : "r"(a), "r"(b)); return r;
}
__device__ __forceinline__ unsigned hmax2(unsigned a, unsigned b) {
    unsigned r; asm("max.f16x2 %0, %1, %2;" : "=r"(r) : "r"(a), "r"(b)); return r;
}
__device__ __forceinline__ float hsum(unsigned u) {
    float lo, hi;
    asm("{\n\t.reg .f16 a, b;\n\tmov.b32 {a, b}, %2;\n\tcvt.f32.f16 %0, a;\n\tcvt.f32.f16 %1, b;\n\t}"
        : "=f"(lo), "=f"(hi) : "r"(u));
    return lo + hi;
}

// swizzled uint4 index within a [GG][8]-uint4 frame (zero padding, conflict-free)
#define SWZ(cell, q) (((cell) << 3) + ((q) ^ ((cell) & 7)))

// s0 frame gets one extra all-zero row (cell index GG) for clamped pool neighbors
#define S0_ROWS (GG + 1)
#define SMEM_BYTES ((S0_ROWS * 8 + GG * 8) * 16 + 3 * GG * 4)  // 68,736 B -> 3 blocks/SM

// blocks [0,npair): pair blocks (thread = cell); [npair,npair+nimg): image blocks.
__global__ __launch_bounds__(256, 3) void fused_kernel(const float* __restrict__ zw,
                                                       const float* __restrict__ zp,
                                                       const float* __restrict__ fl,
                                                       const void* __restrict__ gs,
                                                       float* __restrict__ out,
                                                       int B, int npair, int nimg) {
    extern __shared__ char smraw[];
    __shared__ double rd[4];
    __shared__ unsigned isLast;
    int tid = threadIdx.x;
    int blk = blockIdx.x;
    int slot = blk & 15;
    if (tid < 4) rd[tid] = 0.0;

    if (blk < npair) {
        // ================= pair block: wl / pool / objects =================
        uint4* s0b = (uint4*)smraw;            // frame t fp16 [GG+1][8]; row GG = zeros
        uint4* s1b = s0b + S0_ROWS * 8;        // frame t+1 fp16 [GG][8]
        float* p0s = (float*)(s1b + GG * 8);
        float* p1s = p0s + GG;
        float* n1s = p1s + GG;                 // reciprocal norms of frame t+1 cells

        int b = blk % B, t = blk / B;
        size_t f0 = (size_t)(t * B + b);
        size_t f1 = f0 + B;
        const float4* g0 = (const float4*)(zw + f0 * (GG * DD));
        const float4* g1 = (const float4*)(zw + f1 * (GG * DD));

        p0s[tid] = zp[f0 * GG + tid];
        p1s[tid] = zp[f1 * GG + tid];
        if (tid < 32) ((unsigned*)(s0b + GG * 8))[tid] = 0u;   // zero row

        // coalesced load: exact fp32 z_what_loss (packed) + swizzled fp16 frames
        const u64 NEG1 = 0xBF800000BF800000ULL;
        u64 wl2 = 0ULL;
#pragma unroll
        for (int it = 0; it < 16; ++it) {
            int idx = it * 256 + tid;
            float4 a = g0[idx];
            float4 v = g1[idx];
            u64 d01 = ffma2(mkf(a.x, a.y), NEG1, mkf(v.x, v.y));
            u64 d23 = ffma2(mkf(a.z, a.w), NEG1, mkf(v.z, v.w));
            wl2 = ffma2(d01, d01, wl2);
            wl2 = ffma2(d23, d23, wl2);
            int cell = idx >> 4, d4 = idx & 15;
            int u2idx = SWZ(cell, d4 >> 1) * 2 + (d4 & 1);
            uint2 pa, pb;
            pa.x = pkh(a.x, a.y);  pa.y = pkh(a.z, a.w);
            pb.x = pkh(v.x, v.y);  pb.y = pkh(v.z, v.w);
            ((uint2*)s0b)[u2idx] = pa;
            ((uint2*)s1b)[u2idx] = pb;
        }
        float wl = lohisum(wl2);
        __syncthreads();

        int c = tid;
        int i = c >> 4, j = c & 15;
        int cb = c << 3, cx = c & 7;
        float p0c = p0s[c], p1c = p1s[c];
        unsigned z0h = pkh(p0c, p0c);

        // wrapped neighbor indexing (objects term, frame t+1) + pres mask
        int nb8[9];
        unsigned pmask = 0;
        {
            int k = 0;
#pragma unroll
            for (int di = -1; di <= 1; ++di)
#pragma unroll
                for (int dj = -1; dj <= 1; ++dj, ++k) {
                    int nc = ((i + di) & 15) * 16 + ((j + dj) & 15);
                    nb8[k] = nc << 3;
                    if (p1s[nc] > THRS) pmask |= (1u << k);
                }
        }

        // ---- loop A: prior norm + 9 wrapped dots + in-place transform ----
        // fp16x2 accumulators; after the loop, s0[c] = |s0[c]|*p0[c] (fp16)
        unsigned dacc[9] = {0u, 0u, 0u, 0u, 0u, 0u, 0u, 0u, 0u};
        unsigned pna = 0u, pnb = 0u;
#pragma unroll
        for (int q = 0; q < 8; ++q) {
            int off = q ^ cx;
            uint4 pu = s0b[cb + off];
            const unsigned* pw = (const unsigned*)&pu;
            pna = hfma2(pw[0], pw[0], pna);
            pnb = hfma2(pw[1], pw[1], pnb);
            pna = hfma2(pw[2], pw[2], pna);
            pnb = hfma2(pw[3], pw[3], pnb);
#pragma unroll
            for (int k = 0; k < 9; ++k) {
                uint4 nu = s1b[nb8[k] + (q ^ ((nb8[k] >> 3) & 7))];
                const unsigned* nw = (const unsigned*)&nu;
                unsigned d = dacc[k];
                d = hfma2(pw[0], nw[0], d);
                d = hfma2(pw[1], nw[1], d);
                d = hfma2(pw[2], nw[2], d);
                d = hfma2(pw[3], nw[3], d);
                dacc[k] = d;
            }
            uint4 tw;
            tw.x = hmul2(pw[0] & 0x7FFF7FFFu, z0h);
            tw.y = hmul2(pw[1] & 0x7FFF7FFFu, z0h);
            tw.z = hmul2(pw[2] & 0x7FFF7FFFu, z0h);
            tw.w = hmul2(pw[3] & 0x7FFF7FFFu, z0h);
            s0b[cb + off] = tw;
        }
        float pn = hsum(pna) + hsum(pnb);
        float dotf[9];
#pragma unroll
        for (int k = 0; k < 9; ++k) dotf[k] = hsum(dacc[k]);
        __syncthreads();   // all rows transformed

        // clamped pool indexing: out-of-grid -> zero row (cell GG)
        int cb8[9];
        {
            int k = 0;
#pragma unroll
            for (int di = -1; di <= 1; ++di)
#pragma unroll
                for (int dj = -1; dj <= 1; ++dj, ++k) {
                    int ii = i + di, jj = j + dj;
                    bool inb = (ii >= 0 && ii < G && jj >= 0 && jj < G);
                    cb8[k] = (inb ? (ii * 16 + jj) : GG) << 3;
                }
        }

        // ---- loop B: 3x3 max of transformed s0 + pool partials (fp16x2) ----
        unsigned cna = 0u, pda = 0u, naa = 0u;
#pragma unroll
        for (int q = 0; q < 8; ++q) {
            uint4 cu = s1b[cb + (q ^ cx)];
            const unsigned* cw = (const unsigned*)&cu;
            unsigned ca[4];
#pragma unroll
            for (int w = 0; w < 4; ++w) {
                ca[w] = cw[w] & 0x7FFF7FFFu;
                cna = hfma2(ca[w], ca[w], cna);
            }
            unsigned mb0 = 0u, mb1 = 0u, mb2 = 0u, mb3 = 0u;
#pragma unroll
            for (int k = 0; k < 9; ++k) {
                uint4 su = s0b[cb8[k] + (q ^ ((cb8[k] >> 3) & 7))];
                mb0 = hmax2(mb0, su.x);
                mb1 = hmax2(mb1, su.y);
                mb2 = hmax2(mb2, su.z);
                mb3 = hmax2(mb3, su.w);
            }
            pda = hfma2(mb0, ca[0], pda);
            naa = hfma2(mb0, mb0, naa);
            pda = hfma2(mb1, ca[1], pda);
            naa = hfma2(mb1, mb1, naa);
            pda = hfma2(mb2, ca[2], pda);
            naa = hfma2(mb2, mb2, naa);
            pda = hfma2(mb3, ca[3], pda);
            naa = hfma2(mb3, mb3, naa);
        }
        float cn = hsum(cna), pd = hsum(pda), na = hsum(naa);

        n1s[c] = fminf(rsqrtf(cn), 1e8f);    // 1/max(sqrt(cn),~0)
        __syncthreads();

        float rpn = fminf(rsqrtf(pn), 1e8f);
        float ssum = 0.f, smax = -INFINITY;
#pragma unroll
        for (int k = 0; k < 9; ++k) {
            float s = dotf[k] * rpn * n1s[nb8[k] >> 3];
            if (pmask & (1u << k)) {
                ssum += s;
                smax = fmaxf(smax, s);
            }
        }
        float obj = (p0c > THRS && pmask) ? (-5.0f * smax + ssum) : 0.f;
        float nb = fmaxf(p1c * sqrtf(cn), 1e-6f);
        float cosp = __fdividef(pd * p1c, fmaxf(sqrtf(na), 1e-6f) * nb);
        float pool = -cosp * 0.5f * (p0c + p1c);

        wl = wsum(wl); pool = wsum(pool); obj = wsum(obj);
        if ((tid & 31) == 0) {
            atomicAdd(&rd[0], (double)wl);
            atomicAdd(&rd[1], (double)pool);
            atomicAdd(&rd[2], (double)obj);
        }
        __syncthreads();
        if (tid == 0) {
            atomicAdd(&g_slot[0][slot], rd[0]);
            atomicAdd(&g_slot[1][slot], rd[1]);
            atomicAdd(&g_slot[2][slot], rd[2]);
        }
    } else {
        // ================= image block: pres triples + flow term =================
        float* sp = (float*)smraw;
        int n = blk - npair;
        int t = n / B;
        int c = tid;

        float zpc = zp[(size_t)n * GG + c];
        sp[c] = zpc;
        __syncthreads();

        int i = c >> 4, j = c & 15;
        float mx = -INFINITY;
#pragma unroll
        for (int di = -1; di <= 1; ++di) {
            int ii = i + di;
            if (ii < 0 || ii >= G) continue;
#pragma unroll
            for (int dj = -1; dj <= 1; ++dj) {
                int jj = j + dj;
                if (jj < 0 || jj >= G) continue;
                mx = fmaxf(mx, sp[ii * G + jj]);
            }
        }

        float f = fl[(size_t)n * GG + c];
        float fsq = (f > 0.5f) ? (mx - f) * (mx - f) : 0.f;

        float pres = 0.f;
        if (t >= 1 && t <= TT - 2) {
            float za = zp[(size_t)(n - B) * GG + c];
            float zb = zp[(size_t)(n + B) * GG + c];
            float dba = zb - za;
            float sim = 1.f - dba * dba;
            float d1 = zb - zpc, d2 = za - zpc;
            pres += sim * (d1 * d1 + d2 * d2);
        }

        float v0 = wsum(fsq), v1 = wsum(zpc), v2 = wsum(f), v3 = wsum(pres);
        if ((c & 31) == 0) {
            atomicAdd(&rd[0], (double)v0);
            atomicAdd(&rd[1], (double)v1);
            atomicAdd(&rd[2], (double)v2);
            atomicAdd(&rd[3], (double)v3);
        }
        __syncthreads();
        if (tid == 0) {
            atomicAdd(&g_slot[4][slot], rd[0]);
            atomicAdd(&g_slot[5][slot], rd[1]);
            atomicAdd(&g_slot[6][slot], rd[2]);
            atomicAdd(&g_slot[3][slot], rd[3]);
        }
    }

    // ================= last-block finalize =================
    if (tid == 0) {
        __threadfence();
        unsigned old = atomicAdd(&g_ctr, 1u);
        isLast = (old == (unsigned)(npair + nimg) - 1u) ? 1u : 0u;
    }
    __syncthreads();

    if (isLast && tid == 0) {
        __threadfence();
        double acc[7];
#pragma unroll
        for (int q = 0; q < 7; ++q) {
            double s = 0.0;
#pragma unroll
            for (int r = 0; r < 16; ++r) { s += g_slot[q][r]; g_slot[q][r] = 0.0; }
            acc[q] = s;
        }
        g_ctr = 0u;

        int gi = *(const int*)gs;
        double gstep = (gi < 0 || gi > 1000000000) ? (double)__int_as_float(gi) : (double)gi;

        double scale_obj = gstep / 200000.0;        if (scale_obj > 1.0) scale_obj = 1.0;
        double scale_flow = 1.0 - gstep / 100000.0; if (scale_flow < 0.0) scale_flow = 0.0;

        double hinge = acc[5] - acc[6];
        if (hinge < 0.0) hinge = 0.0;
        double flow_loss = acc[4] + 100.0 * hinge;

        double loss = acc[0]                        // z_what_loss (ADJ_W=1)
                    + acc[3]                        // z_pres_loss (PRES_W=1)
                    + acc[1]                        // pool (POOL_W=1)
                    + acc[2] * scale_obj * 10.0     // objects * OBJ_W
                    + flow_loss * scale_flow;       // FLOW_W=1
        out[0] = (float)loss;
    }
}

extern "C" void kernel_launch(void* const* d_in, const int* in_sizes, int n_in,
                              void* d_out, int out_size) {
    const float* zw = (const float*)d_in[0];
    const float* zp = (const float*)d_in[1];
    const float* fl = (const float*)d_in[2];
    const void*  gs = d_in[3];
    int B = in_sizes[0] / (TT * GG * DD);

    static int configured = 0;
    if (!configured) {
        cudaFuncSetAttribute(fused_kernel, cudaFuncAttributeMaxDynamicSharedMemorySize, SMEM_BYTES);
        configured = 1;
    }

    int npair = (TT - 1) * B;
    int nimg  = TT * B;
    fused_kernel<<<npair + nimg, 256, SMEM_BYTES>>>(zw, zp, fl, gs, (float*)d_out, B, npair, nimg);
}

// round 11
// speedup vs baseline: 1.0919x; 1.0919x over previous
#include <cuda_runtime.h>
#include <cuda_fp16.h>

#define TT 8
#define G  16
#define GG 256
#define DD 64
#define THRS 0.5f

// slot-spread accumulators: 0 wl, 1 pool, 2 obj, 3 pres, 4 flowsq, 5 sumzp, 6 sumflow
__device__ double g_slot[7][16];
__device__ unsigned g_ctr;

typedef unsigned long long u64;

__device__ __forceinline__ float wsum(float v) {
#pragma unroll
    for (int s = 16; s > 0; s >>= 1) v += __shfl_xor_sync(0xffffffffu, v, s);
    return v;
}

// ---- packed f32x2 helpers (exact wl path) ----
__device__ __forceinline__ u64 mkf(float lo, float hi) {
    u64 r; asm("mov.b64 %0, {%1, %2};" : "=l"(r) : "f"(lo), "f"(hi)); return r;
}
__device__ __forceinline__ u64 ffma2(u64 a, u64 b, u64 c) {
    u64 r; asm("fma.rn.f32x2 %0, %1, %2, %3;" : "=l"(r) : "l"(a), "l"(b), "l"(c)); return r;
}
__device__ __forceinline__ float lohisum(u64 v) {
    unsigned a, b; asm("mov.b64 {%0, %1}, %2;" : "=r"(a), "=r"(b) : "l"(v));
    return __uint_as_float(a) + __uint_as_float(b);
}

// ---- fp16x2 helpers ----
__device__ __forceinline__ unsigned pkh(float e0, float e1) {
    unsigned r;
    asm("cvt.rn.f16x2.f32 %0, %1, %2;" : "=r"(r) : "f"(e1), "f"(e0));
    return r;  // e0 lo half, e1 hi half
}
__device__ __forceinline__ unsigned hfma2(unsigned a, unsigned b, unsigned c) {
    unsigned r; asm("fma.rn.f16x2 %0, %1, %2, %3;" : "=r"(r) : "r"(a), "r"(b), "r"(c)); return r;
}
__device__ __forceinline__ unsigned hmul2(unsigned a, unsigned b) {
    unsigned r; asm("mul.rn.f16x2 %0, %1, %2;" : "=r"(r) : "r"(a), "r"(b)); return r;
}
__device__ __forceinline__ unsigned hmax2(unsigned a, unsigned b) {
    unsigned r; asm("max.f16x2 %0, %1, %2;" : "=r"(r) : "r"(a), "r"(b)); return r;
}
__device__ __forceinline__ float hsum(unsigned u) {
    float lo, hi;
    asm("{\n\t.reg .f16 a, b;\n\tmov.b32 {a, b}, %2;\n\tcvt.f32.f16 %0, a;\n\tcvt.f32.f16 %1, b;\n\t}"
        : "=f"(lo), "=f"(hi) : "r"(u));
    return lo + hi;
}

// swizzled uint4 index within a [GG][8]-uint4 frame (zero padding, conflict-free)
#define SWZ(cell, q) (((cell) << 3) + ((q) ^ ((cell) & 7)))

// s0 frame gets one extra all-zero row (cell index GG) for clamped pool neighbors
#define S0_ROWS (GG + 1)
#define SMEM_BYTES ((S0_ROWS * 8 + GG * 8) * 16 + 3 * GG * 4)  // 68,736 B -> 3 blocks/SM

// One block per (t,t+1,b) pair; thread = cell. Pres/flow terms folded in.
__global__ __launch_bounds__(256, 3) void fused_kernel(const float* __restrict__ zw,
                                                       const float* __restrict__ zp,
                                                       const float* __restrict__ fl,
                                                       const void* __restrict__ gs,
                                                       float* __restrict__ out,
                                                       int B, int npair) {
    extern __shared__ char smraw[];
    __shared__ double rd[7];
    __shared__ unsigned isLast;
    int tid = threadIdx.x;
    int blk = blockIdx.x;
    int slot = blk & 15;
    if (tid < 7) rd[tid] = 0.0;

    uint4* s0b = (uint4*)smraw;            // frame t fp16 [GG+1][8]; row GG = zeros
    uint4* s1b = s0b + S0_ROWS * 8;        // frame t+1 fp16 [GG][8]
    float* p0s = (float*)(s1b + GG * 8);
    float* p1s = p0s + GG;
    float* n1s = p1s + GG;                 // reciprocal norms of frame t+1 cells

    int b = blk % B, t = blk / B;
    size_t f0 = (size_t)(t * B + b);
    size_t f1 = f0 + B;
    const float4* g0 = (const float4*)(zw + f0 * (GG * DD));
    const float4* g1 = (const float4*)(zw + f1 * (GG * DD));

    p0s[tid] = zp[f0 * GG + tid];
    p1s[tid] = zp[f1 * GG + tid];
    if (tid < 32) ((unsigned*)(s0b + GG * 8))[tid] = 0u;   // zero row

    // coalesced load: exact fp32 z_what_loss (packed) + swizzled fp16 frames
    const u64 NEG1 = 0xBF800000BF800000ULL;
    u64 wl2 = 0ULL;
#pragma unroll
    for (int it = 0; it < 16; ++it) {
        int idx = it * 256 + tid;
        float4 a = g0[idx];
        float4 v = g1[idx];
        u64 d01 = ffma2(mkf(a.x, a.y), NEG1, mkf(v.x, v.y));
        u64 d23 = ffma2(mkf(a.z, a.w), NEG1, mkf(v.z, v.w));
        wl2 = ffma2(d01, d01, wl2);
        wl2 = ffma2(d23, d23, wl2);
        int cell = idx >> 4, d4 = idx & 15;
        int u2idx = SWZ(cell, d4 >> 1) * 2 + (d4 & 1);
        uint2 pa, pb;
        pa.x = pkh(a.x, a.y);  pa.y = pkh(a.z, a.w);
        pb.x = pkh(v.x, v.y);  pb.y = pkh(v.z, v.w);
        ((uint2*)s0b)[u2idx] = pa;
        ((uint2*)s1b)[u2idx] = pb;
    }
    float wl = lohisum(wl2);
    __syncthreads();

    int c = tid;
    int i = c >> 4, j = c & 15;
    int cb = c << 3, cx = c & 7;
    float p0c = p0s[c], p1c = p1s[c];
    unsigned z0h = pkh(p0c, p0c);

    // ---- folded pres/flow terms for image t (and image 7 when t == TT-2) ----
    float fsq = 0.f, szp = 0.f, sfl = 0.f, pres = 0.f;
    {
        float f = fl[f0 * GG + c];
        float mx = -INFINITY;
#pragma unroll
        for (int di = -1; di <= 1; ++di) {
            int ii = i + di;
            if (ii < 0 || ii >= G) continue;
#pragma unroll
            for (int dj = -1; dj <= 1; ++dj) {
                int jj = j + dj;
                if (jj < 0 || jj >= G) continue;
                mx = fmaxf(mx, p0s[ii * G + jj]);
            }
        }
        fsq = (f > 0.5f) ? (mx - f) * (mx - f) : 0.f;
        szp = p0c;
        sfl = f;
        if (t >= 1) {   // pres triple centered at t (t = 1..TT-2 covered by blocks 1..6)
            float za = zp[(f0 - B) * GG + c];
            float zb = p1c;
            float dba = zb - za;
            float sim = 1.f - dba * dba;
            float d1 = zb - p0c, d2 = za - p0c;
            pres = sim * (d1 * d1 + d2 * d2);
        }
        if (t == TT - 2) {   // last pair block also handles image TT-1
            float f7 = fl[f1 * GG + c];
            float mx7 = -INFINITY;
#pragma unroll
            for (int di = -1; di <= 1; ++di) {
                int ii = i + di;
                if (ii < 0 || ii >= G) continue;
#pragma unroll
                for (int dj = -1; dj <= 1; ++dj) {
                    int jj = j + dj;
                    if (jj < 0 || jj >= G) continue;
                    mx7 = fmaxf(mx7, p1s[ii * G + jj]);
                }
            }
            fsq += (f7 > 0.5f) ? (mx7 - f7) * (mx7 - f7) : 0.f;
            szp += p1c;
            sfl += f7;
        }
    }

    // wrapped neighbor indexing (objects term, frame t+1) + pres mask
    int nb8[9];
    unsigned pmask = 0;
    {
        int k = 0;
#pragma unroll
        for (int di = -1; di <= 1; ++di)
#pragma unroll
            for (int dj = -1; dj <= 1; ++dj, ++k) {
                int nc = ((i + di) & 15) * 16 + ((j + dj) & 15);
                nb8[k] = nc << 3;
                if (p1s[nc] > THRS) pmask |= (1u << k);
            }
    }

    // ---- loop A: prior norm + 9 wrapped dots + in-place transform ----
    unsigned dacc[9] = {0u, 0u, 0u, 0u, 0u, 0u, 0u, 0u, 0u};
    unsigned pna = 0u, pnb = 0u;
#pragma unroll
    for (int q = 0; q < 8; ++q) {
        int off = q ^ cx;
        uint4 pu = s0b[cb + off];
        const unsigned* pw = (const unsigned*)&pu;
        pna = hfma2(pw[0], pw[0], pna);
        pnb = hfma2(pw[1], pw[1], pnb);
        pna = hfma2(pw[2], pw[2], pna);
        pnb = hfma2(pw[3], pw[3], pnb);
#pragma unroll
        for (int k = 0; k < 9; ++k) {
            uint4 nu = s1b[nb8[k] + (q ^ ((nb8[k] >> 3) & 7))];
            const unsigned* nw = (const unsigned*)&nu;
            unsigned d = dacc[k];
            d = hfma2(pw[0], nw[0], d);
            d = hfma2(pw[1], nw[1], d);
            d = hfma2(pw[2], nw[2], d);
            d = hfma2(pw[3], nw[3], d);
            dacc[k] = d;
        }
        uint4 tw;
        tw.x = hmul2(pw[0] & 0x7FFF7FFFu, z0h);
        tw.y = hmul2(pw[1] & 0x7FFF7FFFu, z0h);
        tw.z = hmul2(pw[2] & 0x7FFF7FFFu, z0h);
        tw.w = hmul2(pw[3] & 0x7FFF7FFFu, z0h);
        s0b[cb + off] = tw;
    }
    float pn = hsum(pna) + hsum(pnb);
    float dotf[9];
#pragma unroll
    for (int k = 0; k < 9; ++k) dotf[k] = hsum(dacc[k]);
    __syncthreads();   // all rows transformed

    // clamped pool indexing: out-of-grid -> zero row (cell GG)
    int cb8[9];
    {
        int k = 0;
#pragma unroll
        for (int di = -1; di <= 1; ++di)
#pragma unroll
            for (int dj = -1; dj <= 1; ++dj, ++k) {
                int ii = i + di, jj = j + dj;
                bool inb = (ii >= 0 && ii < G && jj >= 0 && jj < G);
                cb8[k] = (inb ? (ii * 16 + jj) : GG) << 3;
            }
    }

    // ---- loop B: 3x3 max of transformed s0 + pool partials (fp16x2) ----
    unsigned cna = 0u, pda = 0u, naa = 0u;
#pragma unroll
    for (int q = 0; q < 8; ++q) {
        uint4 cu = s1b[cb + (q ^ cx)];
        const unsigned* cw = (const unsigned*)&cu;
        unsigned ca[4];
#pragma unroll
        for (int w = 0; w < 4; ++w) {
            ca[w] = cw[w] & 0x7FFF7FFFu;
            cna = hfma2(ca[w], ca[w], cna);
        }
        unsigned mb0 = 0u, mb1 = 0u, mb2 = 0u, mb3 = 0u;
#pragma unroll
        for (int k = 0; k < 9; ++k) {
            uint4 su = s0b[cb8[k] + (q ^ ((cb8[k] >> 3) & 7))];
            mb0 = hmax2(mb0, su.x);
            mb1 = hmax2(mb1, su.y);
            mb2 = hmax2(mb2, su.z);
            mb3 = hmax2(mb3, su.w);
        }
        pda = hfma2(mb0, ca[0], pda);
        naa = hfma2(mb0, mb0, naa);
        pda = hfma2(mb1, ca[1], pda);
        naa = hfma2(mb1, mb1, naa);
        pda = hfma2(mb2, ca[2], pda);
        naa = hfma2(mb2, mb2, naa);
        pda = hfma2(mb3, ca[3], pda);
        naa = hfma2(mb3, mb3, naa);
    }
    float cn = hsum(cna), pd = hsum(pda), na = hsum(naa);

    n1s[c] = fminf(rsqrtf(cn), 1e8f);    // 1/max(sqrt(cn),~0)
    __syncthreads();

    float rpn = fminf(rsqrtf(pn), 1e8f);
    float ssum = 0.f, smax = -INFINITY;
#pragma unroll
    for (int k = 0; k < 9; ++k) {
        float s = dotf[k] * rpn * n1s[nb8[k] >> 3];
        if (pmask & (1u << k)) {
            ssum += s;
            smax = fmaxf(smax, s);
        }
    }
    float obj = (p0c > THRS && pmask) ? (-5.0f * smax + ssum) : 0.f;
    float nb = fmaxf(p1c * sqrtf(cn), 1e-6f);
    float cosp = __fdividef(pd * p1c, fmaxf(sqrtf(na), 1e-6f) * nb);
    float pool = -cosp * 0.5f * (p0c + p1c);

    wl = wsum(wl); pool = wsum(pool); obj = wsum(obj);
    pres = wsum(pres); fsq = wsum(fsq); szp = wsum(szp); sfl = wsum(sfl);
    if ((tid & 31) == 0) {
        atomicAdd(&rd[0], (double)wl);
        atomicAdd(&rd[1], (double)pool);
        atomicAdd(&rd[2], (double)obj);
        atomicAdd(&rd[3], (double)pres);
        atomicAdd(&rd[4], (double)fsq);
        atomicAdd(&rd[5], (double)szp);
        atomicAdd(&rd[6], (double)sfl);
    }
    __syncthreads();
    if (tid == 0) {
#pragma unroll
        for (int q = 0; q < 7; ++q) atomicAdd(&g_slot[q][slot], rd[q]);
    }

    // ================= last-block finalize =================
    if (tid == 0) {
        __threadfence();
        unsigned old = atomicAdd(&g_ctr, 1u);
        isLast = (old == (unsigned)npair - 1u) ? 1u : 0u;
    }
    __syncthreads();

    if (isLast && tid == 0) {
        __threadfence();
        double acc[7];
#pragma unroll
        for (int q = 0; q < 7; ++q) {
            double s = 0.0;
#pragma unroll
            for (int r = 0; r < 16; ++r) { s += g_slot[q][r]; g_slot[q][r] = 0.0; }
            acc[q] = s;
        }
        g_ctr = 0u;

        int gi = *(const int*)gs;
        double gstep = (gi < 0 || gi > 1000000000) ? (double)__int_as_float(gi) : (double)gi;

        double scale_obj = gstep / 200000.0;        if (scale_obj > 1.0) scale_obj = 1.0;
        double scale_flow = 1.0 - gstep / 100000.0; if (scale_flow < 0.0) scale_flow = 0.0;

        double hinge = acc[5] - acc[6];
        if (hinge < 0.0) hinge = 0.0;
        double flow_loss = acc[4] + 100.0 * hinge;

        double loss = acc[0]                        // z_what_loss (ADJ_W=1)
                    + acc[3]                        // z_pres_loss (PRES_W=1)
                    + acc[1]                        // pool (POOL_W=1)
                    + acc[2] * scale_obj * 10.0     // objects * OBJ_W
                    + flow_loss * scale_flow;       // FLOW_W=1
        out[0] = (float)loss;
    }
}

extern "C" void kernel_launch(void* const* d_in, const int* in_sizes, int n_in,
                              void* d_out, int out_size) {
    const float* zw = (const float*)d_in[0];
    const float* zp = (const float*)d_in[1];
    const float* fl = (const float*)d_in[2];
    const void*  gs = d_in[3];
    int B = in_sizes[0] / (TT * GG * DD);

    static int configured = 0;
    if (!configured) {
        cudaFuncSetAttribute(fused_kernel, cudaFuncAttributeMaxDynamicSharedMemorySize, SMEM_BYTES);
        configured = 1;
    }

    int npair = (TT - 1) * B;
    fused_kernel<<<npair, 256, SMEM_BYTES>>>(zw, zp, fl, gs, (float*)d_out, B, npair);
}